// round 1
// baseline (speedup 1.0000x reference)
#include <cuda_runtime.h>
#include <math.h>

#define IM     256
#define NSP    288
#define NSAMP  640
#define MTOT   (NSP*NSAMP)        // 184320
#define NCHUNK 36                 // spoke chunks for adjoint partials
#define SPC    (NSP/NCHUNK)       // 8 spokes per chunk
#define ORTHO_F (1.0f/256.0f)     // 1/sqrt(256*256)

// Scratch (allocation-free rule: __device__ globals)
__device__ float2 g_kdc[MTOT];                 // blended k-space, 1.5 MB
__device__ float2 g_part[NCHUNK*IM*IM];        // adjoint partials, 18.9 MB

__device__ __forceinline__ float2 cmulf(float2 a, float2 b) {
    return make_float2(fmaf(a.x, b.x, -(a.y*b.y)), fmaf(a.x, b.y, a.y*b.x));
}
__device__ __forceinline__ float2 expif(float t) {
    float s, c; sincosf(t, &s, &c); return make_float2(c, s);
}

// ---------------------------------------------------------------------------
// Kernel A: forward NDFT + DCF + sigmoid blend.  One thread per k-sample m.
// A[m] = ORTHO * sum_u e^{-i kx u} * ( sum_w img[u,w] e^{-i ky w} ) reordered:
// stream image in (256 u x 16 w) SMEM panels; per panel keep 16 complex
// accumulators over u (phase via recurrence), then fold with e^{-i ky w}.
// ---------------------------------------------------------------------------
#define BN 16
__global__ void __launch_bounds__(256) fwd_kernel(
    const float2* __restrict__ img,          // [256][256] (re,im)
    const float2* __restrict__ yrad,         // [640][288] (re,im)
    const float*  __restrict__ lambda_param, // [1]
    const float*  __restrict__ kx,           // [M]
    const float*  __restrict__ ky)           // [M]
{
    __shared__ float2 panel[IM*BN];          // 32 KB, [u][w]

    const int m   = blockIdx.x * 256 + threadIdx.x;
    const float kxm = kx[m];
    const float kym = ky[m];

    const float2 stepx = expif(-kxm);          // e^{-i kx} per u step
    const float2 ex0   = expif(128.0f * kxm);  // e^{-i kx * (-128)}
    float2 A = make_float2(0.0f, 0.0f);

    #pragma unroll 1
    for (int p = 0; p < IM/BN; ++p) {
        __syncthreads();
        // cooperative load of panel p (coalesced: consecutive tid -> consecutive w)
        for (int idx = threadIdx.x; idx < IM*BN; idx += 256) {
            int u = idx >> 4, w = idx & (BN-1);
            panel[idx] = img[u*IM + p*BN + w];
        }
        __syncthreads();

        float2 acc[BN];
        #pragma unroll
        for (int w = 0; w < BN; ++w) acc[w] = make_float2(0.0f, 0.0f);

        float2 ex = ex0;
        #pragma unroll 2
        for (int u = 0; u < IM; ++u) {
            const float4* row = reinterpret_cast<const float4*>(&panel[u*BN]);
            #pragma unroll
            for (int w2 = 0; w2 < BN/2; ++w2) {
                float4 d = row[w2];                 // 2 complex pixels (broadcast LDS)
                float2 a0 = acc[2*w2], a1 = acc[2*w2+1];
                a0.x = fmaf(ex.x, d.x, a0.x); a0.x = fmaf(-ex.y, d.y, a0.x);
                a0.y = fmaf(ex.x, d.y, a0.y); a0.y = fmaf( ex.y, d.x, a0.y);
                a1.x = fmaf(ex.x, d.z, a1.x); a1.x = fmaf(-ex.y, d.w, a1.x);
                a1.y = fmaf(ex.x, d.w, a1.y); a1.y = fmaf( ex.y, d.z, a1.y);
                acc[2*w2] = a0; acc[2*w2+1] = a1;
            }
            ex = cmulf(ex, stepx);
        }

        // fold panel accumulators with e^{-i ky * v}, v = p*BN + w - 128
        float2 ey = expif(-kym * (float)(p*BN - 128));
        const float2 stepy = expif(-kym);
        #pragma unroll
        for (int w = 0; w < BN; ++w) {
            A.x = fmaf(acc[w].x, ey.x, A.x); A.x = fmaf(-acc[w].y, ey.y, A.x);
            A.y = fmaf(acc[w].x, ey.y, A.y); A.y = fmaf( acc[w].y, ey.x, A.y);
            ey = cmulf(ey, stepy);
        }
    }

    // epilogue: ortho scale, ramp DCF, sigmoid blend with measured data
    A.x *= ORTHO_F; A.y *= ORTHO_F;
    const float lam = 1.0f / (1.0f + expf(-lambda_param[0]));
    const float dcf = sqrtf(kxm*kxm + kym*kym);
    const int t = m % NSAMP, s = m / NSAMP;
    const float2 yv = yrad[t*NSP + s];          // y_radial is (640, 288, 2)
    const float a = lam * dcf, b = 1.0f - lam;
    g_kdc[m] = make_float2(fmaf(a, A.x, b*yv.x), fmaf(a, A.y, b*yv.y));
}

// ---------------------------------------------------------------------------
// Kernel B: adjoint NDFT.  x[u,w] += sum_m k[m] e^{i kx u} e^{i ky w}.
// Within a spoke kx,ky are linear in sample index t, so both phase factors are
// geometric recurrences over t (slope fitted from spoke endpoints for accuracy).
// Block: 128u x 64w output tile, thread: 8x4 register tile. Grid.y = spoke
// chunks -> deterministic partials, reduced by Kernel C.
// ---------------------------------------------------------------------------
__global__ void __launch_bounds__(256) adj_kernel(
    const float* __restrict__ kx, const float* __restrict__ ky)
{
    const int u0 = (blockIdx.x & 1) * 128;
    const int w0 = (blockIdx.x >> 1) * 64;
    const int chunk = blockIdx.y;
    const int tr = threadIdx.x >> 4;   // 0..15
    const int tc = threadIdx.x & 15;   // 0..15

    float U[8], W[4];
    #pragma unroll
    for (int i = 0; i < 8; ++i) U[i] = (float)(u0 + tr + i*16 - 128);
    #pragma unroll
    for (int j = 0; j < 4; ++j) W[j] = (float)(w0 + tc + j*16 - 128);

    float2 acc[8][4];
    #pragma unroll
    for (int i = 0; i < 8; ++i)
        #pragma unroll
        for (int j = 0; j < 4; ++j) acc[i][j] = make_float2(0.0f, 0.0f);

    #pragma unroll 1
    for (int sp = 0; sp < SPC; ++sp) {
        const int s  = chunk*SPC + sp;
        const int m0 = s*NSAMP;
        const float kx0 = kx[m0], ky0 = ky[m0];
        // endpoint-fitted slope: slope error ~1e-9 -> phase error ~1e-4 rad max
        const float dkx = (kx[m0+NSAMP-1] - kx0) * (1.0f/(float)(NSAMP-1));
        const float dky = (ky[m0+NSAMP-1] - ky0) * (1.0f/(float)(NSAMP-1));

        float2 pu[8], su[8], pw[4], sw[4];
        #pragma unroll
        for (int i = 0; i < 8; ++i) { pu[i] = expif(kx0*U[i]); su[i] = expif(dkx*U[i]); }
        #pragma unroll
        for (int j = 0; j < 4; ++j) { pw[j] = expif(ky0*W[j]); sw[j] = expif(dky*W[j]); }

        #pragma unroll 2
        for (int t = 0; t < NSAMP; ++t) {
            const float2 k = g_kdc[m0 + t];    // uniform address -> L1 broadcast
            float2 qw[4];
            #pragma unroll
            for (int j = 0; j < 4; ++j) qw[j] = cmulf(k, pw[j]);
            #pragma unroll
            for (int i = 0; i < 8; ++i) {
                const float2 p = pu[i];
                #pragma unroll
                for (int j = 0; j < 4; ++j) {
                    float2 a = acc[i][j];
                    a.x = fmaf(p.x, qw[j].x, a.x); a.x = fmaf(-p.y, qw[j].y, a.x);
                    a.y = fmaf(p.x, qw[j].y, a.y); a.y = fmaf( p.y, qw[j].x, a.y);
                    acc[i][j] = a;
                }
                pu[i] = cmulf(pu[i], su[i]);
            }
            #pragma unroll
            for (int j = 0; j < 4; ++j) pw[j] = cmulf(pw[j], sw[j]);
        }
    }

    float2* part = g_part + (size_t)chunk * (IM*IM);
    #pragma unroll
    for (int i = 0; i < 8; ++i)
        #pragma unroll
        for (int j = 0; j < 4; ++j)
            part[(u0 + tr + i*16)*IM + (w0 + tc + j*16)] = acc[i][j];
}

// ---------------------------------------------------------------------------
// Kernel C: deterministic partial reduction + ortho scale + (re,im) interleave.
// ---------------------------------------------------------------------------
__global__ void __launch_bounds__(256) reduce_kernel(float* __restrict__ out)
{
    const int idx = blockIdx.x * 256 + threadIdx.x;  // 0 .. 65535 (u*256+w)
    float2 sum = make_float2(0.0f, 0.0f);
    #pragma unroll
    for (int c = 0; c < NCHUNK; ++c) {
        const float2 v = g_part[(size_t)c*(IM*IM) + idx];
        sum.x += v.x; sum.y += v.y;
    }
    out[2*idx]   = sum.x * ORTHO_F;
    out[2*idx+1] = sum.y * ORTHO_F;
}

extern "C" void kernel_launch(void* const* d_in, const int* in_sizes, int n_in,
                              void* d_out, int out_size)
{
    const float2* img  = (const float2*)d_in[0];  // x: (1,1,256,256,2)
    const float2* yrad = (const float2*)d_in[1];  // y_radial: (640,288,2)
    const float*  lam  = (const float*)d_in[2];   // lambda_param: (1,)
    const float*  ktr  = (const float*)d_in[3];   // ktraj: (1,2,M)
    const float*  kx = ktr;
    const float*  ky = ktr + MTOT;

    fwd_kernel<<<MTOT/256, 256>>>(img, yrad, lam, kx, ky);
    adj_kernel<<<dim3(8, NCHUNK), 256>>>(kx, ky);
    reduce_kernel<<<(IM*IM)/256, 256>>>((float*)d_out);
}